// round 8
// baseline (speedup 1.0000x reference)
#include <cuda_runtime.h>
#include <float.h>

#define NB    4
#define NP    64
#define BP    256           // NB*NP query rows
#define D     768
#define NN    2048
#define RR    12
#define TOPK  16
#define KSPLIT 4
#define ADJ_BLOCKS 1184
#define SCORE_BLOCKS 128    // (NN/64) * (BP/64)

// ---- scratch (static __device__, no allocations) ----
__device__ float g_rnorm[NN];             // 1/||keys_param row||
__device__ float g_scores[BP * NN];       // scores               2.0 MB
__device__ float g_adjsum[NN * NN];       // sum_r adjacency     16.8 MB
__device__ float g_nei[BP * NN];          //                      2.0 MB
__device__ float g_part[KSPLIT][BP * D];  // split-K partials     3.1 MB

#define FMA_F32X2(d, a, b, c) \
    asm("fma.rn.f32x2 %0, %1, %2, %3;" : "=l"(d) : "l"(a), "l"(b), "l"(c))

// ---------------------------------------------------------------------------
// K1 mega-kernel (block-specialized):
//   blocks [0, ADJ_BLOCKS):            adj_sum = sum_r adjacency[r]  (201 MB)
//   blocks [ADJ_BLOCKS, +SCORE_BLOCKS): scores tile GEMM with inline rnorm
// The scores blocks ride along under the HBM stream of the adjsum blocks.
// ---------------------------------------------------------------------------
__global__ void k_mega(const float* __restrict__ adj,
                       const float* __restrict__ kp,
                       const float* __restrict__ pos) {
    if (blockIdx.x < ADJ_BLOCKS) {
        // ---- adjsum: 2 float4 sites per step (~24 outstanding LDGs) ----
        const long long t4 = (long long)NN * NN / 4;
        const long long S = (long long)ADJ_BLOCKS * 256;
        const float4* a = (const float4*)adj;
        float4* o = (float4*)g_adjsum;
        for (long long i = (long long)blockIdx.x * 256 + threadIdx.x; i < t4; i += 2 * S) {
            long long j = i + S;
            bool h2 = j < t4;
            float4 acc0 = __ldcs(&a[i]);
            float4 acc1 = h2 ? __ldcs(&a[j]) : make_float4(0.f, 0.f, 0.f, 0.f);
            #pragma unroll
            for (int r = 1; r < RR; r++) {
                float4 v0 = __ldcs(&a[i + (long long)r * t4]);
                float4 v1 = h2 ? __ldcs(&a[j + (long long)r * t4]) : make_float4(0.f, 0.f, 0.f, 0.f);
                acc0.x += v0.x; acc0.y += v0.y; acc0.z += v0.z; acc0.w += v0.w;
                acc1.x += v1.x; acc1.y += v1.y; acc1.z += v1.z; acc1.w += v1.w;
            }
            o[i] = acc0;
            if (h2) o[j] = acc1;
        }
        return;
    }

    // ---- scores: BM=64, BN=64, BK=16, f32x2 FFMA2, inline rnorm ----
    __shared__ float Asd[16][132];   // duplicated pairs Asd[k][2m]=Asd[k][2m+1]
    __shared__ float Bs[16][68];
    __shared__ float srn[64];
    int s = blockIdx.x - ADJ_BLOCKS;
    int n0 = (s & 31) * 64, m0 = (s >> 5) * 64;
    int t = threadIdx.x;
    int w = t >> 5, lane = t & 31;

    // inline rnorm for this block's 64 key rows (warp w -> rows rr*8+w)
    #pragma unroll 1
    for (int rr = 0; rr < 8; rr++) {
        int r = rr * 8 + w;
        const float* src = kp + (long long)(n0 + r) * D;
        float ss = 0.f;
        #pragma unroll
        for (int i = 0; i < D / 32; i++) { float v = src[i * 32 + lane]; ss += v * v; }
        #pragma unroll
        for (int o = 16; o; o >>= 1) ss += __shfl_xor_sync(0xffffffff, ss, o);
        if (lane == 0) srn[r] = rsqrtf(ss + 1e-12f);
    }
    __syncthreads();
    if (m0 == 0 && t < 64) g_rnorm[n0 + t] = srn[t];   // publish for k_out_part

    int tx = t & 15, ty = t >> 4;        // tx: n-quad, ty: m-quad
    int am = t >> 2, aq = t & 3;         // loader mapping (64 rows x 4 quads)
    float brn = srn[am];
    unsigned long long acc[4][2] = {};
    for (int k0 = 0; k0 < D; k0 += 16) {
        float4 av = *(const float4*)&pos[(long long)(m0 + am) * D + k0 + aq * 4];
        float2 d0 = {av.x, av.x}, d1 = {av.y, av.y}, d2 = {av.z, av.z}, d3 = {av.w, av.w};
        *(float2*)&Asd[aq * 4 + 0][2 * am] = d0;
        *(float2*)&Asd[aq * 4 + 1][2 * am] = d1;
        *(float2*)&Asd[aq * 4 + 2][2 * am] = d2;
        *(float2*)&Asd[aq * 4 + 3][2 * am] = d3;
        float4 bv = *(const float4*)&kp[(long long)(n0 + am) * D + k0 + aq * 4];
        Bs[aq * 4 + 0][am] = bv.x * brn;
        Bs[aq * 4 + 1][am] = bv.y * brn;
        Bs[aq * 4 + 2][am] = bv.z * brn;
        Bs[aq * 4 + 3][am] = bv.w * brn;
        __syncthreads();
        #pragma unroll
        for (int kk = 0; kk < 16; kk++) {
            ulonglong2 a01 = *(const ulonglong2*)&Asd[kk][ty * 8];
            ulonglong2 a23 = *(const ulonglong2*)&Asd[kk][ty * 8 + 4];
            ulonglong2 bb  = *(const ulonglong2*)&Bs[kk][tx * 4];
            FMA_F32X2(acc[0][0], a01.x, bb.x, acc[0][0]);
            FMA_F32X2(acc[0][1], a01.x, bb.y, acc[0][1]);
            FMA_F32X2(acc[1][0], a01.y, bb.x, acc[1][0]);
            FMA_F32X2(acc[1][1], a01.y, bb.y, acc[1][1]);
            FMA_F32X2(acc[2][0], a23.x, bb.x, acc[2][0]);
            FMA_F32X2(acc[2][1], a23.x, bb.y, acc[2][1]);
            FMA_F32X2(acc[3][0], a23.y, bb.x, acc[3][0]);
            FMA_F32X2(acc[3][1], a23.y, bb.y, acc[3][1]);
        }
        __syncthreads();
    }
    #pragma unroll
    for (int mm = 0; mm < 4; mm++) {
        float2 lo = *(float2*)&acc[mm][0];
        float2 hi = *(float2*)&acc[mm][1];
        float4 o = {lo.x, lo.y, hi.x, hi.y};
        *(float4*)&g_scores[(long long)(m0 + ty * 4 + mm) * NN + n0 + tx * 4] = o;
    }
}

// ---------------------------------------------------------------------------
// K2: fused top-16 + softmax + nei gather.  Block per row.
// Warps lane-sort-8 + 16 shfl pops -> 8 sorted 16-lists; warp0 merges and
// builds softmax weights in smem; then all warps gather-blend 16 adjsum rows.
// ---------------------------------------------------------------------------
__global__ void k_topknei() {
    int row = blockIdx.x;
    int w = threadIdx.x >> 5, lane = threadIdx.x & 31;
    int tid = threadIdx.x;
    __shared__ float cv[8][TOPK];
    __shared__ int   ci[8][TOPK];
    __shared__ float swgt[TOPK];
    __shared__ int   sid[TOPK];

    const float4* src = (const float4*)(g_scores + (long long)row * NN);
    float4 x = src[w * 64 + lane];
    float4 y = src[w * 64 + 32 + lane];
    int b0 = (w * 64 + lane) * 4, b1 = (w * 64 + 32 + lane) * 4;
    float v[8]  = {x.x, x.y, x.z, x.w, y.x, y.y, y.z, y.w};
    int   id[8] = {b0, b0 + 1, b0 + 2, b0 + 3, b1, b1 + 1, b1 + 2, b1 + 3};

    // descending sort, tie -> smaller index (19-CE Batcher network)
    #define CE(i, j) do {                                                 \
        float _av = v[i], _bv = v[j]; int _ai = id[i], _bi = id[j];       \
        bool _sw = (_bv > _av) || (_bv == _av && _bi < _ai);              \
        v[i]  = _sw ? _bv : _av;  id[i] = _sw ? _bi : _ai;                \
        v[j]  = _sw ? _av : _bv;  id[j] = _sw ? _ai : _bi;                \
    } while (0)
    CE(0,1); CE(2,3); CE(4,5); CE(6,7);
    CE(0,2); CE(1,3); CE(4,6); CE(5,7);
    CE(1,2); CE(5,6);
    CE(0,4); CE(1,5); CE(2,6); CE(3,7);
    CE(2,4); CE(3,5);
    CE(1,2); CE(3,4); CE(5,6);
    #undef CE

    // 16 pops: warp argmax over lane heads
    #pragma unroll 1
    for (int r = 0; r < TOPK; r++) {
        float wv = v[0]; int wi = id[0];
        #pragma unroll
        for (int o = 16; o; o >>= 1) {
            float ov = __shfl_xor_sync(0xffffffff, wv, o);
            int   oi = __shfl_xor_sync(0xffffffff, wi, o);
            if (ov > wv || (ov == wv && oi < wi)) { wv = ov; wi = oi; }
        }
        if (wi == id[0]) {
            #pragma unroll
            for (int q = 0; q < 7; q++) { v[q] = v[q + 1]; id[q] = id[q + 1]; }
            v[7] = -FLT_MAX; id[7] = 1 << 30;
        }
        if (lane == 0) { cv[w][r] = wv; ci[w][r] = wi; }
    }
    __syncthreads();

    // warp 0 merges the 8 sorted 16-lists, builds softmax weights in smem
    if (w == 0) {
        __shared__ float rv_[TOPK];
        int p = 0;
        #pragma unroll 1
        for (int r = 0; r < TOPK; r++) {
            float hv = (lane < 8) ? cv[lane][p] : -FLT_MAX;
            int   hi = (lane < 8) ? ci[lane][p] : (1 << 30);
            float wv = hv; int wi = hi;
            #pragma unroll
            for (int o = 16; o; o >>= 1) {
                float ov = __shfl_xor_sync(0xffffffff, wv, o);
                int   oi = __shfl_xor_sync(0xffffffff, wi, o);
                if (ov > wv || (ov == wv && oi < wi)) { wv = ov; wi = oi; }
            }
            if (lane < 8 && wi == hi) p++;
            if (lane == 0) { rv_[r] = wv; sid[r] = wi; }
        }
        __syncwarp();
        if (lane < TOPK) {                         // parallel softmax (16 lanes)
            float e = expf(rv_[lane] - rv_[0]);
            float sum = e;
            #pragma unroll
            for (int o = 1; o < TOPK; o <<= 1)
                sum += __shfl_xor_sync(0xffff, sum, o);
            swgt[lane] = e / sum;
        }
    }
    __syncthreads();

    // nei gather: nei[row,:] = sum_k swgt[k] * adjsum[sid[k], :]
    float wgt[TOPK]; int idn[TOPK];
    #pragma unroll
    for (int k = 0; k < TOPK; k++) { wgt[k] = swgt[k]; idn[k] = sid[k]; }
    const float4* a4 = (const float4*)g_adjsum;
    float4* n4 = (float4*)g_nei;
    #pragma unroll
    for (int c = tid; c < NN / 4; c += 256) {
        float4 acc = {0.f, 0.f, 0.f, 0.f};
        #pragma unroll
        for (int k = 0; k < TOPK; k++) {
            float4 vv = a4[(long long)idn[k] * (NN / 4) + c];
            float wk = wgt[k];
            acc.x += wk * vv.x; acc.y += wk * vv.y; acc.z += wk * vv.z; acc.w += wk * vv.w;
        }
        n4[(long long)row * (NN / 4) + c] = acc;
    }
}

// ---------------------------------------------------------------------------
// K3: partial[z][m,d] = sum_{n in z-chunk} nei[m,n]*kp[n,d]*rnorm[n]
// BM=64, BN=64, BK=16, split-K=4, f32x2
// ---------------------------------------------------------------------------
__global__ void k_out_part(const float* __restrict__ kp) {
    __shared__ float Asd[16][132];
    __shared__ float Bs[16][68];
    int d0 = blockIdx.x * 64, m0 = blockIdx.y * 64;
    int kz = blockIdx.z;
    int t = threadIdx.x;
    int tx = t & 15, ty = t >> 4;
    int am = t >> 2, aq = t & 3;         // A loader
    int bk = t >> 4, bq = t & 15;        // B loader: 16 k-rows x 16 d-quads
    unsigned long long acc[4][2] = {};
    for (int k0 = kz * (NN / KSPLIT); k0 < (kz + 1) * (NN / KSPLIT); k0 += 16) {
        float4 av = *(const float4*)&g_nei[(long long)(m0 + am) * NN + k0 + aq * 4];
        float2 d0v = {av.x, av.x}, d1v = {av.y, av.y}, d2v = {av.z, av.z}, d3v = {av.w, av.w};
        *(float2*)&Asd[aq * 4 + 0][2 * am] = d0v;
        *(float2*)&Asd[aq * 4 + 1][2 * am] = d1v;
        *(float2*)&Asd[aq * 4 + 2][2 * am] = d2v;
        *(float2*)&Asd[aq * 4 + 3][2 * am] = d3v;
        float brn = g_rnorm[k0 + bk];
        float4 bv = *(const float4*)&kp[(long long)(k0 + bk) * D + d0 + bq * 4];
        bv.x *= brn; bv.y *= brn; bv.z *= brn; bv.w *= brn;
        *(float4*)&Bs[bk][bq * 4] = bv;
        __syncthreads();
        #pragma unroll
        for (int kk = 0; kk < 16; kk++) {
            ulonglong2 a01 = *(const ulonglong2*)&Asd[kk][ty * 8];
            ulonglong2 a23 = *(const ulonglong2*)&Asd[kk][ty * 8 + 4];
            ulonglong2 bb  = *(const ulonglong2*)&Bs[kk][tx * 4];
            FMA_F32X2(acc[0][0], a01.x, bb.x, acc[0][0]);
            FMA_F32X2(acc[0][1], a01.x, bb.y, acc[0][1]);
            FMA_F32X2(acc[1][0], a01.y, bb.x, acc[1][0]);
            FMA_F32X2(acc[1][1], a01.y, bb.y, acc[1][1]);
            FMA_F32X2(acc[2][0], a23.x, bb.x, acc[2][0]);
            FMA_F32X2(acc[2][1], a23.x, bb.y, acc[2][1]);
            FMA_F32X2(acc[3][0], a23.y, bb.x, acc[3][0]);
            FMA_F32X2(acc[3][1], a23.y, bb.y, acc[3][1]);
        }
        __syncthreads();
    }
    #pragma unroll
    for (int mm = 0; mm < 4; mm++) {
        float2 lo = *(float2*)&acc[mm][0];
        float2 hi = *(float2*)&acc[mm][1];
        float4 o = {lo.x, lo.y, hi.x, hi.y};
        *(float4*)&g_part[kz][(long long)(m0 + ty * 4 + mm) * D + d0 + tx * 4] = o;
    }
}

// K4: out = sum_z partial[z]
__global__ void k_reduce(float* __restrict__ out) {
    int i = blockIdx.x * blockDim.x + threadIdx.x;     // 49152 float4
    const float4* p0 = (const float4*)g_part[0];
    const float4* p1 = (const float4*)g_part[1];
    const float4* p2 = (const float4*)g_part[2];
    const float4* p3 = (const float4*)g_part[3];
    float4 a = p0[i], b = p1[i], c = p2[i], d = p3[i];
    float4 o = {a.x + b.x + c.x + d.x, a.y + b.y + c.y + d.y,
                a.z + b.z + c.z + d.z, a.w + b.w + c.w + d.w};
    ((float4*)out)[i] = o;
}

// ---------------------------------------------------------------------------
extern "C" void kernel_launch(void* const* d_in, const int* in_sizes, int n_in,
                              void* d_out, int out_size) {
    const float* pos = (const float*)d_in[0];   // (4,64,768) f32
    const float* kp  = (const float*)d_in[1];   // (2048,768) f32
    const float* adj = (const float*)d_in[2];   // (12,2048,2048) f32
    float* out = (float*)d_out;                 // (4,64,768) f32

    k_mega<<<ADJ_BLOCKS + SCORE_BLOCKS, 256>>>(adj, kp, pos);
    k_topknei<<<BP, 256>>>();
    k_out_part<<<dim3(D / 64, BP / 64, KSPLIT), 256>>>(kp);
    k_reduce<<<BP * D / 4 / 256, 256>>>(out);
}

// round 10
// speedup vs baseline: 1.5918x; 1.5918x over previous
#include <cuda_runtime.h>
#include <float.h>

#define NB    4
#define NP    64
#define BP    256           // NB*NP query rows
#define D     768
#define NN    2048
#define RR    12
#define TOPK  16
#define KSPLIT 4
#define ADJ_BLOCKS 1184

// ---- scratch (static __device__, no allocations) ----
__device__ float g_rnorm[NN];             // 1/||keys_param row||
__device__ float g_scores[BP * NN];       // scores               2.0 MB
__device__ float g_adjsum[NN * NN];       // sum_r adjacency     16.8 MB
__device__ float g_nei[BP * NN];          //                      2.0 MB
__device__ float g_part[KSPLIT][BP * D];  // split-K partials     3.1 MB

#define FMA_F32X2(d, a, b, c) \
    asm("fma.rn.f32x2 %0, %1, %2, %3;" : "=l"(d) : "l"(a), "l"(b), "l"(c))

// ---------------------------------------------------------------------------
// K1: fused adj_sum (sum_r adjacency, 201 MB stream) + key inverse norms.
// Blocks [0, ADJ_BLOCKS) do adjsum (2 float4 sites/step, ~24 outstanding
// LDGs); blocks [ADJ_BLOCKS, +16) do rnorm. Both branches are lean-register.
// ---------------------------------------------------------------------------
__global__ void k_adjsum_rnorm(const float* __restrict__ adj,
                               const float* __restrict__ kp) {
    if (blockIdx.x >= ADJ_BLOCKS) {
        // ---- rnorm: 16 blocks x 8 warps x 16 rows = 2048 rows ----
        int bb = blockIdx.x - ADJ_BLOCKS;
        int w = threadIdx.x >> 5, lane = threadIdx.x & 31;
        for (int rr = 0; rr < 16; rr++) {
            int row = bb * 128 + rr * 8 + w;
            const float* src = kp + (long long)row * D;
            float ss = 0.f;
            #pragma unroll
            for (int i = 0; i < D / 32; i++) { float v = src[i * 32 + lane]; ss += v * v; }
            #pragma unroll
            for (int o = 16; o; o >>= 1) ss += __shfl_xor_sync(0xffffffff, ss, o);
            if (lane == 0) g_rnorm[row] = rsqrtf(ss + 1e-12f);
        }
        return;
    }
    const long long t4 = (long long)NN * NN / 4;
    const long long S = (long long)ADJ_BLOCKS * 256;
    const float4* a = (const float4*)adj;
    float4* o = (float4*)g_adjsum;
    for (long long i = (long long)blockIdx.x * 256 + threadIdx.x; i < t4; i += 2 * S) {
        long long j = i + S;
        bool h2 = j < t4;
        float4 acc0 = __ldcs(&a[i]);
        float4 acc1 = h2 ? __ldcs(&a[j]) : make_float4(0.f, 0.f, 0.f, 0.f);
        #pragma unroll
        for (int r = 1; r < RR; r++) {
            float4 v0 = __ldcs(&a[i + (long long)r * t4]);
            float4 v1 = h2 ? __ldcs(&a[j + (long long)r * t4]) : make_float4(0.f, 0.f, 0.f, 0.f);
            acc0.x += v0.x; acc0.y += v0.y; acc0.z += v0.z; acc0.w += v0.w;
            acc1.x += v1.x; acc1.y += v1.y; acc1.z += v1.z; acc1.w += v1.w;
        }
        o[i] = acc0;
        if (h2) o[j] = acc1;
    }
}

// ---------------------------------------------------------------------------
// K2: scores[m,n] = sum_d pos[m,d]*kp[n,d]*rnorm[n]  (NT), f32x2 FFMA2
// BM=64, BN=64, BK=16, 256 thr, 4x4 thread tile, A duplicated in smem
// ---------------------------------------------------------------------------
__global__ void k_scores(const float* __restrict__ pos, const float* __restrict__ kp) {
    __shared__ float Asd[16][132];   // duplicated pairs: Asd[k][2m]=Asd[k][2m+1]=A[m][k]
    __shared__ float Bs[16][68];
    int m0 = blockIdx.y * 64, n0 = blockIdx.x * 64;
    int t = threadIdx.x;
    int tx = t & 15, ty = t >> 4;        // tx: n-quad, ty: m-quad
    int am = t >> 2, aq = t & 3;         // loader mapping (64 rows x 4 quads)
    float brn = g_rnorm[n0 + am];        // B row scale (row = n0+am)
    unsigned long long acc[4][2] = {};
    for (int k0 = 0; k0 < D; k0 += 16) {
        float4 av = *(const float4*)&pos[(long long)(m0 + am) * D + k0 + aq * 4];
        float2 d0 = {av.x, av.x}, d1 = {av.y, av.y}, d2 = {av.z, av.z}, d3 = {av.w, av.w};
        *(float2*)&Asd[aq * 4 + 0][2 * am] = d0;
        *(float2*)&Asd[aq * 4 + 1][2 * am] = d1;
        *(float2*)&Asd[aq * 4 + 2][2 * am] = d2;
        *(float2*)&Asd[aq * 4 + 3][2 * am] = d3;
        float4 bv = *(const float4*)&kp[(long long)(n0 + am) * D + k0 + aq * 4];
        Bs[aq * 4 + 0][am] = bv.x * brn;
        Bs[aq * 4 + 1][am] = bv.y * brn;
        Bs[aq * 4 + 2][am] = bv.z * brn;
        Bs[aq * 4 + 3][am] = bv.w * brn;
        __syncthreads();
        #pragma unroll
        for (int kk = 0; kk < 16; kk++) {
            ulonglong2 a01 = *(const ulonglong2*)&Asd[kk][ty * 8];
            ulonglong2 a23 = *(const ulonglong2*)&Asd[kk][ty * 8 + 4];
            ulonglong2 bb  = *(const ulonglong2*)&Bs[kk][tx * 4];
            FMA_F32X2(acc[0][0], a01.x, bb.x, acc[0][0]);
            FMA_F32X2(acc[0][1], a01.x, bb.y, acc[0][1]);
            FMA_F32X2(acc[1][0], a01.y, bb.x, acc[1][0]);
            FMA_F32X2(acc[1][1], a01.y, bb.y, acc[1][1]);
            FMA_F32X2(acc[2][0], a23.x, bb.x, acc[2][0]);
            FMA_F32X2(acc[2][1], a23.x, bb.y, acc[2][1]);
            FMA_F32X2(acc[3][0], a23.y, bb.x, acc[3][0]);
            FMA_F32X2(acc[3][1], a23.y, bb.y, acc[3][1]);
        }
        __syncthreads();
    }
    #pragma unroll
    for (int mm = 0; mm < 4; mm++) {
        float2 lo = *(float2*)&acc[mm][0];
        float2 hi = *(float2*)&acc[mm][1];
        float4 o = {lo.x, lo.y, hi.x, hi.y};
        *(float4*)&g_scores[(long long)(m0 + ty * 4 + mm) * NN + n0 + tx * 4] = o;
    }
}

// ---------------------------------------------------------------------------
// K3: fused top-16 + softmax + nei gather.  Block per row, 512 threads.
// Warps 0-7: lane-sort-8 + 16 shfl pops -> 8 sorted 16-lists; warp0 merges
// and builds softmax weights. Then ALL 16 warps gather-blend 16 adjsum rows
// (each thread owns exactly one float4 column).
// ---------------------------------------------------------------------------
__global__ void k_topknei() {
    int row = blockIdx.x;
    int w = threadIdx.x >> 5, lane = threadIdx.x & 31;
    int tid = threadIdx.x;
    __shared__ float cv[8][TOPK];
    __shared__ int   ci[8][TOPK];
    __shared__ float swgt[TOPK];
    __shared__ int   sid[TOPK];
    __shared__ float rv_[TOPK];

    if (w < 8) {
        const float4* src = (const float4*)(g_scores + (long long)row * NN);
        float4 x = src[w * 64 + lane];
        float4 y = src[w * 64 + 32 + lane];
        int b0 = (w * 64 + lane) * 4, b1 = (w * 64 + 32 + lane) * 4;
        float v[8]  = {x.x, x.y, x.z, x.w, y.x, y.y, y.z, y.w};
        int   id[8] = {b0, b0 + 1, b0 + 2, b0 + 3, b1, b1 + 1, b1 + 2, b1 + 3};

        // descending sort, tie -> smaller index (19-CE Batcher network)
        #define CE(i, j) do {                                                 \
            float _av = v[i], _bv = v[j]; int _ai = id[i], _bi = id[j];       \
            bool _sw = (_bv > _av) || (_bv == _av && _bi < _ai);              \
            v[i]  = _sw ? _bv : _av;  id[i] = _sw ? _bi : _ai;                \
            v[j]  = _sw ? _av : _bv;  id[j] = _sw ? _ai : _bi;                \
        } while (0)
        CE(0,1); CE(2,3); CE(4,5); CE(6,7);
        CE(0,2); CE(1,3); CE(4,6); CE(5,7);
        CE(1,2); CE(5,6);
        CE(0,4); CE(1,5); CE(2,6); CE(3,7);
        CE(2,4); CE(3,5);
        CE(1,2); CE(3,4); CE(5,6);
        #undef CE

        // 16 pops: warp argmax over lane heads
        #pragma unroll 1
        for (int r = 0; r < TOPK; r++) {
            float wv = v[0]; int wi = id[0];
            #pragma unroll
            for (int o = 16; o; o >>= 1) {
                float ov = __shfl_xor_sync(0xffffffff, wv, o);
                int   oi = __shfl_xor_sync(0xffffffff, wi, o);
                if (ov > wv || (ov == wv && oi < wi)) { wv = ov; wi = oi; }
            }
            if (wi == id[0]) {
                #pragma unroll
                for (int q = 0; q < 7; q++) { v[q] = v[q + 1]; id[q] = id[q + 1]; }
                v[7] = -FLT_MAX; id[7] = 1 << 30;
            }
            if (lane == 0) { cv[w][r] = wv; ci[w][r] = wi; }
        }
    }
    __syncthreads();

    // warp 0 merges the 8 sorted 16-lists, builds softmax weights in smem
    if (w == 0) {
        int p = 0;
        #pragma unroll 1
        for (int r = 0; r < TOPK; r++) {
            float hv = (lane < 8) ? cv[lane][p] : -FLT_MAX;
            int   hi = (lane < 8) ? ci[lane][p] : (1 << 30);
            float wv = hv; int wi = hi;
            #pragma unroll
            for (int o = 16; o; o >>= 1) {
                float ov = __shfl_xor_sync(0xffffffff, wv, o);
                int   oi = __shfl_xor_sync(0xffffffff, wi, o);
                if (ov > wv || (ov == wv && oi < wi)) { wv = ov; wi = oi; }
            }
            if (lane < 8 && wi == hi) p++;
            if (lane == 0) { rv_[r] = wv; sid[r] = wi; }
        }
        __syncwarp();
        if (lane < TOPK) {                         // parallel softmax (16 lanes)
            float e = expf(rv_[lane] - rv_[0]);
            float sum = e;
            #pragma unroll
            for (int o = 1; o < TOPK; o <<= 1)
                sum += __shfl_xor_sync(0xffff, sum, o);
            swgt[lane] = e / sum;
        }
    }
    __syncthreads();

    // nei gather: each of the 512 threads owns one float4 column
    float wgt[TOPK]; int idn[TOPK];
    #pragma unroll
    for (int k = 0; k < TOPK; k++) { wgt[k] = swgt[k]; idn[k] = sid[k]; }
    const float4* a4 = (const float4*)g_adjsum;
    float4 acc = {0.f, 0.f, 0.f, 0.f};
    #pragma unroll
    for (int k = 0; k < TOPK; k++) {
        float4 vv = a4[(long long)idn[k] * (NN / 4) + tid];
        float wk = wgt[k];
        acc.x += wk * vv.x; acc.y += wk * vv.y; acc.z += wk * vv.z; acc.w += wk * vv.w;
    }
    ((float4*)g_nei)[(long long)row * (NN / 4) + tid] = acc;
}

// ---------------------------------------------------------------------------
// K4: partial[z][m,d] = sum_{n in z-chunk} nei[m,n]*kp[n,d]*rnorm[n]
// BM=64, BN=64, BK=16, split-K=4, f32x2
// ---------------------------------------------------------------------------
__global__ void k_out_part(const float* __restrict__ kp) {
    __shared__ float Asd[16][132];
    __shared__ float Bs[16][68];
    int d0 = blockIdx.x * 64, m0 = blockIdx.y * 64;
    int kz = blockIdx.z;
    int t = threadIdx.x;
    int tx = t & 15, ty = t >> 4;
    int am = t >> 2, aq = t & 3;         // A loader
    int bk = t >> 4, bq = t & 15;        // B loader: 16 k-rows x 16 d-quads
    unsigned long long acc[4][2] = {};
    for (int k0 = kz * (NN / KSPLIT); k0 < (kz + 1) * (NN / KSPLIT); k0 += 16) {
        float4 av = *(const float4*)&g_nei[(long long)(m0 + am) * NN + k0 + aq * 4];
        float2 d0v = {av.x, av.x}, d1v = {av.y, av.y}, d2v = {av.z, av.z}, d3v = {av.w, av.w};
        *(float2*)&Asd[aq * 4 + 0][2 * am] = d0v;
        *(float2*)&Asd[aq * 4 + 1][2 * am] = d1v;
        *(float2*)&Asd[aq * 4 + 2][2 * am] = d2v;
        *(float2*)&Asd[aq * 4 + 3][2 * am] = d3v;
        float brn = g_rnorm[k0 + bk];
        float4 bv = *(const float4*)&kp[(long long)(k0 + bk) * D + d0 + bq * 4];
        bv.x *= brn; bv.y *= brn; bv.z *= brn; bv.w *= brn;
        *(float4*)&Bs[bk][bq * 4] = bv;
        __syncthreads();
        #pragma unroll
        for (int kk = 0; kk < 16; kk++) {
            ulonglong2 a01 = *(const ulonglong2*)&Asd[kk][ty * 8];
            ulonglong2 a23 = *(const ulonglong2*)&Asd[kk][ty * 8 + 4];
            ulonglong2 bb  = *(const ulonglong2*)&Bs[kk][tx * 4];
            FMA_F32X2(acc[0][0], a01.x, bb.x, acc[0][0]);
            FMA_F32X2(acc[0][1], a01.x, bb.y, acc[0][1]);
            FMA_F32X2(acc[1][0], a01.y, bb.x, acc[1][0]);
            FMA_F32X2(acc[1][1], a01.y, bb.y, acc[1][1]);
            FMA_F32X2(acc[2][0], a23.x, bb.x, acc[2][0]);
            FMA_F32X2(acc[2][1], a23.x, bb.y, acc[2][1]);
            FMA_F32X2(acc[3][0], a23.y, bb.x, acc[3][0]);
            FMA_F32X2(acc[3][1], a23.y, bb.y, acc[3][1]);
        }
        __syncthreads();
    }
    #pragma unroll
    for (int mm = 0; mm < 4; mm++) {
        float2 lo = *(float2*)&acc[mm][0];
        float2 hi = *(float2*)&acc[mm][1];
        float4 o = {lo.x, lo.y, hi.x, hi.y};
        *(float4*)&g_part[kz][(long long)(m0 + ty * 4 + mm) * D + d0 + tx * 4] = o;
    }
}

// K5: out = sum_z partial[z]
__global__ void k_reduce(float* __restrict__ out) {
    int i = blockIdx.x * blockDim.x + threadIdx.x;     // 49152 float4
    const float4* p0 = (const float4*)g_part[0];
    const float4* p1 = (const float4*)g_part[1];
    const float4* p2 = (const float4*)g_part[2];
    const float4* p3 = (const float4*)g_part[3];
    float4 a = p0[i], b = p1[i], c = p2[i], d = p3[i];
    float4 o = {a.x + b.x + c.x + d.x, a.y + b.y + c.y + d.y,
                a.z + b.z + c.z + d.z, a.w + b.w + c.w + d.w};
    ((float4*)out)[i] = o;
}

// ---------------------------------------------------------------------------
extern "C" void kernel_launch(void* const* d_in, const int* in_sizes, int n_in,
                              void* d_out, int out_size) {
    const float* pos = (const float*)d_in[0];   // (4,64,768) f32
    const float* kp  = (const float*)d_in[1];   // (2048,768) f32
    const float* adj = (const float*)d_in[2];   // (12,2048,2048) f32
    float* out = (float*)d_out;                 // (4,64,768) f32

    k_adjsum_rnorm<<<ADJ_BLOCKS + 16, 256>>>(adj, kp);
    k_scores<<<dim3(NN / 64, BP / 64), 256>>>(pos, kp);
    k_topknei<<<BP, 512>>>();
    k_out_part<<<dim3(D / 64, BP / 64, KSPLIT), 256>>>(kp);
    k_reduce<<<BP * D / 4 / 256, 256>>>(out);
}

// round 11
// speedup vs baseline: 1.8847x; 1.1840x over previous
#include <cuda_runtime.h>
#include <float.h>

#define NB    4
#define NP    64
#define BP    256           // NB*NP query rows
#define D     768
#define NN    2048
#define RR    12
#define TOPK  16
#define KSPLIT 8            // split-K for out GEMM
#define DSPLIT 2            // split-D for scores GEMM
#define ADJ_BLOCKS 1184

// ---- scratch (static __device__, no allocations) ----
__device__ float g_rnorm[NN];              // 1/||keys_param row||
__device__ float g_spart[DSPLIT][BP * NN]; // scores partials      4.0 MB
__device__ float g_adjsum[NN * NN];        // sum_r adjacency     16.8 MB
__device__ float g_nei[BP * NN];           //                      2.0 MB
__device__ float g_part[KSPLIT][BP * D];   // split-K partials     6.3 MB

#define FMA_F32X2(d, a, b, c) \
    asm("fma.rn.f32x2 %0, %1, %2, %3;" : "=l"(d) : "l"(a), "l"(b), "l"(c))

// ---------------------------------------------------------------------------
// K1: fused adj_sum (sum_r adjacency, 201 MB stream) + key inverse norms.
// ---------------------------------------------------------------------------
__global__ void k_adjsum_rnorm(const float* __restrict__ adj,
                               const float* __restrict__ kp) {
    if (blockIdx.x >= ADJ_BLOCKS) {
        int bb = blockIdx.x - ADJ_BLOCKS;
        int w = threadIdx.x >> 5, lane = threadIdx.x & 31;
        for (int rr = 0; rr < 16; rr++) {
            int row = bb * 128 + rr * 8 + w;
            const float* src = kp + (long long)row * D;
            float ss = 0.f;
            #pragma unroll
            for (int i = 0; i < D / 32; i++) { float v = src[i * 32 + lane]; ss += v * v; }
            #pragma unroll
            for (int o = 16; o; o >>= 1) ss += __shfl_xor_sync(0xffffffff, ss, o);
            if (lane == 0) g_rnorm[row] = rsqrtf(ss + 1e-12f);
        }
        return;
    }
    const long long t4 = (long long)NN * NN / 4;
    const long long S = (long long)ADJ_BLOCKS * 256;
    const float4* a = (const float4*)adj;
    float4* o = (float4*)g_adjsum;
    for (long long i = (long long)blockIdx.x * 256 + threadIdx.x; i < t4; i += 2 * S) {
        long long j = i + S;
        bool h2 = j < t4;
        float4 acc0 = __ldcs(&a[i]);
        float4 acc1 = h2 ? __ldcs(&a[j]) : make_float4(0.f, 0.f, 0.f, 0.f);
        #pragma unroll
        for (int r = 1; r < RR; r++) {
            float4 v0 = __ldcs(&a[i + (long long)r * t4]);
            float4 v1 = h2 ? __ldcs(&a[j + (long long)r * t4]) : make_float4(0.f, 0.f, 0.f, 0.f);
            acc0.x += v0.x; acc0.y += v0.y; acc0.z += v0.z; acc0.w += v0.w;
            acc1.x += v1.x; acc1.y += v1.y; acc1.z += v1.z; acc1.w += v1.w;
        }
        o[i] = acc0;
        if (h2) o[j] = acc1;
    }
}

// ---------------------------------------------------------------------------
// K2: spart[z][m,n] = sum_{d in z-half} pos[m,d]*kp[n,d]*rnorm[n]  (NT)
// BM=64, BN=64, BK=32, 256 thr, 4x4 thread tile, f32x2, split-D=2
// ---------------------------------------------------------------------------
__global__ void k_scores(const float* __restrict__ pos, const float* __restrict__ kp) {
    __shared__ float Asd[32][132];   // dup pairs: Asd[k][2m]=Asd[k][2m+1]=A[m][k]
    __shared__ float Bs[32][68];
    int m0 = blockIdx.y * 64, n0 = blockIdx.x * 64;
    int z = blockIdx.z;
    int t = threadIdx.x;
    int tx = t & 15, ty = t >> 4;        // tx: n-quad, ty: m-quad
    int am = t >> 2, aq = t & 3;         // loaders: 64 rows x quads {aq, aq+4}
    float brn = g_rnorm[n0 + am];
    unsigned long long acc[4][2] = {};
    for (int k0 = z * (D / DSPLIT); k0 < (z + 1) * (D / DSPLIT); k0 += 32) {
        #pragma unroll
        for (int h = 0; h < 2; h++) {
            int q = aq + 4 * h;
            float4 av = *(const float4*)&pos[(long long)(m0 + am) * D + k0 + q * 4];
            float2 p0 = {av.x, av.x}, p1 = {av.y, av.y}, p2 = {av.z, av.z}, p3 = {av.w, av.w};
            *(float2*)&Asd[q * 4 + 0][2 * am] = p0;
            *(float2*)&Asd[q * 4 + 1][2 * am] = p1;
            *(float2*)&Asd[q * 4 + 2][2 * am] = p2;
            *(float2*)&Asd[q * 4 + 3][2 * am] = p3;
            float4 bv = *(const float4*)&kp[(long long)(n0 + am) * D + k0 + q * 4];
            Bs[q * 4 + 0][am] = bv.x * brn;
            Bs[q * 4 + 1][am] = bv.y * brn;
            Bs[q * 4 + 2][am] = bv.z * brn;
            Bs[q * 4 + 3][am] = bv.w * brn;
        }
        __syncthreads();
        #pragma unroll
        for (int kk = 0; kk < 32; kk++) {
            ulonglong2 a01 = *(const ulonglong2*)&Asd[kk][ty * 8];
            ulonglong2 a23 = *(const ulonglong2*)&Asd[kk][ty * 8 + 4];
            ulonglong2 bb  = *(const ulonglong2*)&Bs[kk][tx * 4];
            FMA_F32X2(acc[0][0], a01.x, bb.x, acc[0][0]);
            FMA_F32X2(acc[0][1], a01.x, bb.y, acc[0][1]);
            FMA_F32X2(acc[1][0], a01.y, bb.x, acc[1][0]);
            FMA_F32X2(acc[1][1], a01.y, bb.y, acc[1][1]);
            FMA_F32X2(acc[2][0], a23.x, bb.x, acc[2][0]);
            FMA_F32X2(acc[2][1], a23.x, bb.y, acc[2][1]);
            FMA_F32X2(acc[3][0], a23.y, bb.x, acc[3][0]);
            FMA_F32X2(acc[3][1], a23.y, bb.y, acc[3][1]);
        }
        __syncthreads();
    }
    #pragma unroll
    for (int mm = 0; mm < 4; mm++) {
        float2 lo = *(float2*)&acc[mm][0];
        float2 hi = *(float2*)&acc[mm][1];
        float4 o = {lo.x, lo.y, hi.x, hi.y};
        *(float4*)&g_spart[z][(long long)(m0 + ty * 4 + mm) * NN + n0 + tx * 4] = o;
    }
}

// ---------------------------------------------------------------------------
// K3: fused (scores partial sum) + top-16 + softmax + nei gather.
// Block per row, 512 threads. Warps 0-7 sort/pop; warp0 merges + softmax;
// all 16 warps gather-blend 16 adjsum rows (one float4 column per thread).
// ---------------------------------------------------------------------------
__global__ void k_topknei() {
    int row = blockIdx.x;
    int w = threadIdx.x >> 5, lane = threadIdx.x & 31;
    int tid = threadIdx.x;
    __shared__ float cv[8][TOPK];
    __shared__ int   ci[8][TOPK];
    __shared__ float swgt[TOPK];
    __shared__ int   sid[TOPK];
    __shared__ float rv_[TOPK];

    if (w < 8) {
        const float4* p0 = (const float4*)(g_spart[0] + (long long)row * NN);
        const float4* p1 = (const float4*)(g_spart[1] + (long long)row * NN);
        float4 xa = p0[w * 64 + lane],      xb = p1[w * 64 + lane];
        float4 ya = p0[w * 64 + 32 + lane], yb = p1[w * 64 + 32 + lane];
        float4 x = {xa.x + xb.x, xa.y + xb.y, xa.z + xb.z, xa.w + xb.w};
        float4 y = {ya.x + yb.x, ya.y + yb.y, ya.z + yb.z, ya.w + yb.w};
        int b0 = (w * 64 + lane) * 4, b1 = (w * 64 + 32 + lane) * 4;
        float v[8]  = {x.x, x.y, x.z, x.w, y.x, y.y, y.z, y.w};
        int   id[8] = {b0, b0 + 1, b0 + 2, b0 + 3, b1, b1 + 1, b1 + 2, b1 + 3};

        // descending sort, tie -> smaller index (19-CE Batcher network)
        #define CE(i, j) do {                                                 \
            float _av = v[i], _bv = v[j]; int _ai = id[i], _bi = id[j];       \
            bool _sw = (_bv > _av) || (_bv == _av && _bi < _ai);              \
            v[i]  = _sw ? _bv : _av;  id[i] = _sw ? _bi : _ai;                \
            v[j]  = _sw ? _av : _bv;  id[j] = _sw ? _ai : _bi;                \
        } while (0)
        CE(0,1); CE(2,3); CE(4,5); CE(6,7);
        CE(0,2); CE(1,3); CE(4,6); CE(5,7);
        CE(1,2); CE(5,6);
        CE(0,4); CE(1,5); CE(2,6); CE(3,7);
        CE(2,4); CE(3,5);
        CE(1,2); CE(3,4); CE(5,6);
        #undef CE

        #pragma unroll 1
        for (int r = 0; r < TOPK; r++) {
            float wv = v[0]; int wi = id[0];
            #pragma unroll
            for (int o = 16; o; o >>= 1) {
                float ov = __shfl_xor_sync(0xffffffff, wv, o);
                int   oi = __shfl_xor_sync(0xffffffff, wi, o);
                if (ov > wv || (ov == wv && oi < wi)) { wv = ov; wi = oi; }
            }
            if (wi == id[0]) {
                #pragma unroll
                for (int q = 0; q < 7; q++) { v[q] = v[q + 1]; id[q] = id[q + 1]; }
                v[7] = -FLT_MAX; id[7] = 1 << 30;
            }
            if (lane == 0) { cv[w][r] = wv; ci[w][r] = wi; }
        }
    }
    __syncthreads();

    if (w == 0) {
        int p = 0;
        #pragma unroll 1
        for (int r = 0; r < TOPK; r++) {
            float hv = (lane < 8) ? cv[lane][p] : -FLT_MAX;
            int   hi = (lane < 8) ? ci[lane][p] : (1 << 30);
            float wv = hv; int wi = hi;
            #pragma unroll
            for (int o = 16; o; o >>= 1) {
                float ov = __shfl_xor_sync(0xffffffff, wv, o);
                int   oi = __shfl_xor_sync(0xffffffff, wi, o);
                if (ov > wv || (ov == wv && oi < wi)) { wv = ov; wi = oi; }
            }
            if (lane < 8 && wi == hi) p++;
            if (lane == 0) { rv_[r] = wv; sid[r] = wi; }
        }
        __syncwarp();
        if (lane < TOPK) {
            float e = expf(rv_[lane] - rv_[0]);
            float sum = e;
            #pragma unroll
            for (int o = 1; o < TOPK; o <<= 1)
                sum += __shfl_xor_sync(0xffff, sum, o);
            swgt[lane] = e / sum;
        }
    }
    __syncthreads();

    float wgt[TOPK]; int idn[TOPK];
    #pragma unroll
    for (int k = 0; k < TOPK; k++) { wgt[k] = swgt[k]; idn[k] = sid[k]; }
    const float4* a4 = (const float4*)g_adjsum;
    float4 acc = {0.f, 0.f, 0.f, 0.f};
    #pragma unroll
    for (int k = 0; k < TOPK; k++) {
        float4 vv = a4[(long long)idn[k] * (NN / 4) + tid];
        float wk = wgt[k];
        acc.x += wk * vv.x; acc.y += wk * vv.y; acc.z += wk * vv.z; acc.w += wk * vv.w;
    }
    ((float4*)g_nei)[(long long)row * (NN / 4) + tid] = acc;
}

// ---------------------------------------------------------------------------
// K4: partial[z][m,d] = sum_{n in z-chunk} nei[m,n]*kp[n,d]*rnorm[n]
// BM=64, BN=64, BK=32, split-K=8, f32x2
// ---------------------------------------------------------------------------
__global__ void k_out_part(const float* __restrict__ kp) {
    __shared__ float Asd[32][132];
    __shared__ float Bs[32][68];
    int d0 = blockIdx.x * 64, m0 = blockIdx.y * 64;
    int kz = blockIdx.z;
    int t = threadIdx.x;
    int tx = t & 15, ty = t >> 4;
    int am = t >> 2, aq = t & 3;         // A loader: 64 rows x quads {aq, aq+4}
    int bk = t >> 4, bq = t & 15;        // B loader: rows {bk, bk+16} x 16 d-quads
    unsigned long long acc[4][2] = {};
    for (int k0 = kz * (NN / KSPLIT); k0 < (kz + 1) * (NN / KSPLIT); k0 += 32) {
        #pragma unroll
        for (int h = 0; h < 2; h++) {
            int q = aq + 4 * h;
            float4 av = *(const float4*)&g_nei[(long long)(m0 + am) * NN + k0 + q * 4];
            float2 p0 = {av.x, av.x}, p1 = {av.y, av.y}, p2 = {av.z, av.z}, p3 = {av.w, av.w};
            *(float2*)&Asd[q * 4 + 0][2 * am] = p0;
            *(float2*)&Asd[q * 4 + 1][2 * am] = p1;
            *(float2*)&Asd[q * 4 + 2][2 * am] = p2;
            *(float2*)&Asd[q * 4 + 3][2 * am] = p3;
            int kr = bk + 16 * h;
            float brn = g_rnorm[k0 + kr];
            float4 bv = *(const float4*)&kp[(long long)(k0 + kr) * D + d0 + bq * 4];
            bv.x *= brn; bv.y *= brn; bv.z *= brn; bv.w *= brn;
            *(float4*)&Bs[kr][bq * 4] = bv;
        }
        __syncthreads();
        #pragma unroll
        for (int kk = 0; kk < 32; kk++) {
            ulonglong2 a01 = *(const ulonglong2*)&Asd[kk][ty * 8];
            ulonglong2 a23 = *(const ulonglong2*)&Asd[kk][ty * 8 + 4];
            ulonglong2 bb  = *(const ulonglong2*)&Bs[kk][tx * 4];
            FMA_F32X2(acc[0][0], a01.x, bb.x, acc[0][0]);
            FMA_F32X2(acc[0][1], a01.x, bb.y, acc[0][1]);
            FMA_F32X2(acc[1][0], a01.y, bb.x, acc[1][0]);
            FMA_F32X2(acc[1][1], a01.y, bb.y, acc[1][1]);
            FMA_F32X2(acc[2][0], a23.x, bb.x, acc[2][0]);
            FMA_F32X2(acc[2][1], a23.x, bb.y, acc[2][1]);
            FMA_F32X2(acc[3][0], a23.y, bb.x, acc[3][0]);
            FMA_F32X2(acc[3][1], a23.y, bb.y, acc[3][1]);
        }
        __syncthreads();
    }
    #pragma unroll
    for (int mm = 0; mm < 4; mm++) {
        float2 lo = *(float2*)&acc[mm][0];
        float2 hi = *(float2*)&acc[mm][1];
        float4 o = {lo.x, lo.y, hi.x, hi.y};
        *(float4*)&g_part[kz][(long long)(m0 + ty * 4 + mm) * D + d0 + tx * 4] = o;
    }
}

// K5: out = sum_z partial[z]
__global__ void k_reduce(float* __restrict__ out) {
    int i = blockIdx.x * blockDim.x + threadIdx.x;     // 49152 float4
    float4 acc = {0.f, 0.f, 0.f, 0.f};
    #pragma unroll
    for (int z = 0; z < KSPLIT; z++) {
        float4 v = ((const float4*)g_part[z])[i];
        acc.x += v.x; acc.y += v.y; acc.z += v.z; acc.w += v.w;
    }
    ((float4*)out)[i] = acc;
}

// ---------------------------------------------------------------------------
extern "C" void kernel_launch(void* const* d_in, const int* in_sizes, int n_in,
                              void* d_out, int out_size) {
    const float* pos = (const float*)d_in[0];   // (4,64,768) f32
    const float* kp  = (const float*)d_in[1];   // (2048,768) f32
    const float* adj = (const float*)d_in[2];   // (12,2048,2048) f32
    float* out = (float*)d_out;                 // (4,64,768) f32

    k_adjsum_rnorm<<<ADJ_BLOCKS + 16, 256>>>(adj, kp);
    k_scores<<<dim3(NN / 64, BP / 64, DSPLIT), 256>>>(pos, kp);
    k_topknei<<<BP, 512>>>();
    k_out_part<<<dim3(D / 64, BP / 64, KSPLIT), 256>>>(kp);
    k_reduce<<<BP * D / 4 / 256, 256>>>(out);
}